// round 4
// baseline (speedup 1.0000x reference)
#include <cuda_runtime.h>
#include <cstdint>

// Problem constants (fixed-shape problem)
#define BB   8
#define CCH  128
#define HH   96
#define WW   160
#define DNUM 81

// Tiling
#define TXW   32          // x pixels per block
#define TYPR  4           // pixel-PAIR rows per block  -> 8 y pixels per block
#define CC    8           // channels per pipeline chunk
#define NCHUNK (CCH / CC) // 16

#define TWO_ROWS  16      // (8 y pixels + 2*4 halo)
#define TWO_PITCH 40      // (32 x + 2*4 halo)
#define ONE_ROWS  8

#define TWO_STAGE_FLOATS (CC * TWO_ROWS * TWO_PITCH)  // 5120
#define ONE_STAGE_FLOATS (CC * ONE_ROWS * TXW)        // 2048
#define SMEM_FLOATS (2 * (TWO_STAGE_FLOATS + ONE_STAGE_FLOATS)) // 14336
#define SMEM_BYTES  (SMEM_FLOATS * 4)                 // 57344

__device__ __forceinline__ void cp16(uint32_t dst, const void* src, int src_bytes) {
    // 16-byte cp.async with ignore-src zero-fill (src_bytes = 0 -> all zeros)
    asm volatile("cp.async.cg.shared.global [%0], [%1], 16, %2;\n"
                 :: "r"(dst), "l"(src), "r"(src_bytes));
}

__device__ __forceinline__ void load_chunk(
    const float* __restrict__ one, const float* __restrict__ two,
    float* two_s, float* one_s,
    int stage, int ccBase, int b, int yb, int x0, int tid)
{
    // ---- two tile: CC x 16 rows x 40 cols = 1280 16B-chunks, 10 per thread ----
    #pragma unroll
    for (int i = 0; i < 10; i++) {
        int t   = tid + i * 128;
        int c   = t / 160;
        int rem = t - c * 160;
        int r   = rem / 10;
        int q   = rem - r * 10;
        int y2  = yb - 4 + r;
        int xs  = x0 - 4 + q * 4;
        bool ok = (y2 >= 0) && (y2 < HH) && (xs >= 0) && (xs <= WW - 4);
        int yc  = min(max(y2, 0), HH - 1);
        int xc  = min(max(xs, 0), WW - 4);
        const float* g = two + (((size_t)b * CCH + ccBase + c) * HH + yc) * WW + xc;
        float* dptr = &two_s[((stage * CC + c) * TWO_ROWS + r) * TWO_PITCH + q * 4];
        uint32_t dst = (uint32_t)__cvta_generic_to_shared(dptr);
        cp16(dst, g, ok ? 16 : 0);
    }
    // ---- one tile: CC x 8 rows x 32 cols = 512 16B-chunks, 4 per thread ----
    #pragma unroll
    for (int i = 0; i < 4; i++) {
        int t   = tid + i * 128;
        int c   = t / 64;
        int rem = t - c * 64;
        int r   = rem / 8;
        int q   = rem - r * 8;
        const float* g = one + (((size_t)b * CCH + ccBase + c) * HH + yb + r) * WW + x0 + q * 4;
        float* dptr = &one_s[((stage * CC + c) * ONE_ROWS + r) * TXW + q * 4];
        uint32_t dst = (uint32_t)__cvta_generic_to_shared(dptr);
        cp16(dst, g, 16);
    }
    asm volatile("cp.async.commit_group;\n");
}

__global__ void __launch_bounds__(128, 2)
ModuleCorrelation_5669356831807_kernel(
    const float* __restrict__ one,
    const float* __restrict__ two,
    float* __restrict__ out)
{
    extern __shared__ float smem[];
    float* two_s = smem;                       // [2][CC][16][40]
    float* one_s = smem + 2 * TWO_STAGE_FLOATS; // [2][CC][8][32]

    const int tx  = threadIdx.x;      // 0..31  -> x within tile (also lane)
    const int typ = threadIdx.y;      // 0..3   -> pixel-pair row
    const int tid = typ * 32 + tx;

    const int x0 = blockIdx.x * TXW;
    const int yb = blockIdx.y * (2 * TYPR);
    const int b  = blockIdx.z;

    float acc0[DNUM];  // pixel (y, x)
    float acc1[DNUM];  // pixel (y+1, x)
    #pragma unroll
    for (int d = 0; d < DNUM; d++) { acc0[d] = 0.0f; acc1[d] = 0.0f; }

    // Prologue: stage chunk 0
    load_chunk(one, two, two_s, one_s, 0, 0, b, yb, x0, tid);

    for (int ch = 0; ch < NCHUNK; ch++) {
        const int s = ch & 1;
        asm volatile("cp.async.wait_group 0;\n" ::: "memory");
        __syncthreads();  // chunk ch visible to all; prev compute fully done

        if (ch + 1 < NCHUNK)
            load_chunk(one, two, two_s, one_s, s ^ 1, (ch + 1) * CC, b, yb, x0, tid);

        const float* ts = &two_s[(s * CC) * (TWO_ROWS * TWO_PITCH) + (2 * typ) * TWO_PITCH + tx];
        const float* os = &one_s[(s * CC) * (ONE_ROWS * TXW) + (2 * typ) * TXW + tx];

        #pragma unroll
        for (int c = 0; c < CC; c++) {
            const float o0 = os[c * (ONE_ROWS * TXW)];
            const float o1 = os[c * (ONE_ROWS * TXW) + TXW];
            const float* tp = ts + c * (TWO_ROWS * TWO_PITCH);
            #pragma unroll
            for (int r = 0; r < 10; r++) {
                #pragma unroll
                for (int j = 0; j < 9; j++) {
                    const float v = tp[r * TWO_PITCH + j];
                    if (r < 9) acc0[r * 9 + j]       = fmaf(o0, v, acc0[r * 9 + j]);
                    if (r > 0) acc1[(r - 1) * 9 + j] = fmaf(o1, v, acc1[(r - 1) * 9 + j]);
                }
            }
        }
    }

    // Epilogue: out[b, d, y, x], plane stride = H*W
    const int y = yb + 2 * typ;
    const int x = x0 + tx;
    const float inv = 1.0f / (float)CCH;
    const size_t plane = (size_t)HH * WW;
    const size_t base = ((size_t)b * DNUM) * plane + (size_t)y * WW + x;
    #pragma unroll
    for (int d = 0; d < DNUM; d++) {
        out[base + (size_t)d * plane]      = acc0[d] * inv;
        out[base + (size_t)d * plane + WW] = acc1[d] * inv;
    }
}

extern "C" void kernel_launch(void* const* d_in, const int* in_sizes, int n_in,
                              void* d_out, int out_size) {
    const float* one = (const float*)d_in[0];
    const float* two = (const float*)d_in[1];
    float* out = (float*)d_out;

    // >48KB dynamic smem requires opt-in (idempotent, graph-capture safe)
    cudaFuncSetAttribute(ModuleCorrelation_5669356831807_kernel,
                         cudaFuncAttributeMaxDynamicSharedMemorySize, SMEM_BYTES);

    dim3 grid(WW / TXW, HH / (2 * TYPR), BB);  // (5, 12, 8) = 480 blocks
    dim3 blk(32, TYPR);                        // 128 threads
    ModuleCorrelation_5669356831807_kernel<<<grid, blk, SMEM_BYTES>>>(one, two, out);
}